// round 4
// baseline (speedup 1.0000x reference)
#include <cuda_runtime.h>
#include <cuda_bf16.h>
#include <cstdint>

// Problem constants
#define Bz 32
#define Lz 512
#define Hz 256
#define ML (Bz*Lz)          // 16384 rows

// ---------------- device scratch (allowed: __device__ globals) ----------------
__device__ float g_Hq[ML*Hz];
__device__ float g_Pp[ML*Hz];
__device__ float g_scores[Bz*Lz*Lz];     // reused in-place as attn
__device__ float g_PC[ML*2*Hz];          // [P | C] concat
__device__ float g_Cg[ML*Hz];            // gated context
__device__ float g_gil[ML*3*Hz];
__device__ float g_gir[ML*3*Hz];
__device__ float g_hstate[2][2][Bz*Hz];  // [dir][buf][b*256+k]
__device__ unsigned g_bar[2];

// ---------------- helpers ----------------
__device__ __forceinline__ float tanh_fast(float x) {
    float y; asm("tanh.approx.f32 %0, %1;" : "=f"(y) : "f"(x)); return y;
}
__device__ __forceinline__ float sigmoidf_(float x) {
    return 1.0f / (1.0f + __expf(-x));
}
__device__ __forceinline__ unsigned ld_acq(const unsigned* p) {
    unsigned v; asm volatile("ld.acquire.gpu.global.u32 %0, [%1];" : "=r"(v) : "l"(p)); return v;
}
__device__ __forceinline__ void red_release_add(unsigned* p, unsigned v) {
    asm volatile("red.release.gpu.global.add.u32 [%0], %1;" :: "l"(p), "r"(v) : "memory");
}

// ---------------- generic SGEMM: C = A @ op(B) + bias, with epilogues ----------
// TRANSB=1: B is N x K (row-major), compute A@B^T.  TRANSB=0: B is K x N.
// EPI 0: +bias ; EPI 1: sigmoid(acc+bias) * aux[row*512+256+col] ; EPI 2: plain
#define BMt 128
#define BNt 128
#define BKt 16
template<int TRANSB, int EPI>
__global__ void __launch_bounds__(256, 2) sgemm_kernel(
    const float* __restrict__ A, const float* __restrict__ Bm,
    const float* __restrict__ bias, const float* __restrict__ aux,
    float* __restrict__ Cc,
    int M, int N, int K,
    long sA, long sB, long sC, int ldc, int coff)
{
    __shared__ float As[BKt][BMt];
    __shared__ float Bs[BKt][BNt];
    int z = blockIdx.z;
    A  += z * sA;
    Bm += z * sB;
    long cbase = (long)z * sC;
    int m0 = blockIdx.y * BMt, n0 = blockIdx.x * BNt;
    int tid = threadIdx.x;

    int arow = tid >> 2;          // 0..63
    int akk  = (tid & 3) * 4;     // 0,4,8,12
    int bkk  = tid >> 5;          // 0..7
    int bcol = (tid & 31) * 4;    // 0..124

    float acc[8][8];
#pragma unroll
    for (int i = 0; i < 8; i++)
#pragma unroll
        for (int j = 0; j < 8; j++) acc[i][j] = 0.f;

    int tr = tid >> 4, tc = tid & 15;

    for (int k0 = 0; k0 < K; k0 += BKt) {
        // A tile
        float4 a0 = *(const float4*)&A[(long)(m0 + arow) * K + k0 + akk];
        float4 a1 = *(const float4*)&A[(long)(m0 + arow + 64) * K + k0 + akk];
        As[akk+0][arow] = a0.x; As[akk+1][arow] = a0.y; As[akk+2][arow] = a0.z; As[akk+3][arow] = a0.w;
        As[akk+0][arow+64] = a1.x; As[akk+1][arow+64] = a1.y; As[akk+2][arow+64] = a1.z; As[akk+3][arow+64] = a1.w;
        // B tile
        if (TRANSB) {
            float4 b0 = *(const float4*)&Bm[(long)(n0 + arow) * K + k0 + akk];
            float4 b1 = *(const float4*)&Bm[(long)(n0 + arow + 64) * K + k0 + akk];
            Bs[akk+0][arow] = b0.x; Bs[akk+1][arow] = b0.y; Bs[akk+2][arow] = b0.z; Bs[akk+3][arow] = b0.w;
            Bs[akk+0][arow+64] = b1.x; Bs[akk+1][arow+64] = b1.y; Bs[akk+2][arow+64] = b1.z; Bs[akk+3][arow+64] = b1.w;
        } else {
            float4 b0 = *(const float4*)&Bm[(long)(k0 + bkk) * N + n0 + bcol];
            float4 b1 = *(const float4*)&Bm[(long)(k0 + bkk + 8) * N + n0 + bcol];
            *(float4*)&Bs[bkk][bcol]     = b0;
            *(float4*)&Bs[bkk+8][bcol]   = b1;
        }
        __syncthreads();
#pragma unroll
        for (int kk = 0; kk < BKt; kk++) {
            float a[8], b[8];
            *(float4*)&a[0] = *(float4*)&As[kk][tr*8];
            *(float4*)&a[4] = *(float4*)&As[kk][tr*8+4];
            *(float4*)&b[0] = *(float4*)&Bs[kk][tc*8];
            *(float4*)&b[4] = *(float4*)&Bs[kk][tc*8+4];
#pragma unroll
            for (int i = 0; i < 8; i++)
#pragma unroll
                for (int j = 0; j < 8; j++) acc[i][j] = fmaf(a[i], b[j], acc[i][j]);
        }
        __syncthreads();
    }
    // epilogue
#pragma unroll
    for (int i = 0; i < 8; i++) {
        int row = m0 + tr*8 + i;
#pragma unroll
        for (int j = 0; j < 8; j++) {
            int col = n0 + tc*8 + j;
            float v = acc[i][j];
            if (EPI == 0) {
                v += bias[col];
            } else if (EPI == 1) {
                float g = sigmoidf_(v + bias[col]);
                v = g * aux[(long)row * 512 + 256 + col];
            }
            Cc[cbase + (long)row * ldc + coff + col] = v;
        }
    }
}

// ---------------- copy P into PC[:, :256] ----------------
__global__ void copyP_kernel(const float* __restrict__ P, float* __restrict__ PC) {
    int i = blockIdx.x * blockDim.x + threadIdx.x;   // over 16384*64 float4
    int r = i >> 6;
    int c4 = i & 63;
    ((float4*)PC)[(long)r * 128 + c4] = ((const float4*)P)[i];
}

// ---------------- scores: s[b,t,l] = ws . tanh(Hq[b,l]+Pp[b,t]) + ws_b ----------------
__global__ void __launch_bounds__(256) scores_kernel(
    const float* __restrict__ Hq, const float* __restrict__ Pp,
    const float* __restrict__ ws_w, const float* __restrict__ ws_b,
    float* __restrict__ scores)
{
    __shared__ float pp[8][256];
    __shared__ float wss[256];
    int b = blockIdx.y;
    int t0 = blockIdx.x * 8;
    int tid = threadIdx.x;
    for (int idx = tid; idx < 8 * 256; idx += 256) {
        int tt = idx >> 8, h = idx & 255;
        pp[tt][h] = Pp[((long)(b * 512 + t0 + tt)) * 256 + h];
    }
    if (tid < 256) wss[tid] = ws_w[tid];
    __syncthreads();
    float wsb = __ldg(ws_b);
    int warp = tid >> 5, lane = tid & 31;
    float wsr[8];
#pragma unroll
    for (int u = 0; u < 8; u++) wsr[u] = wss[lane * 8 + u];

    for (int l = warp; l < 512; l += 8) {
        const float4* hp = (const float4*)(Hq + ((long)(b * 512 + l)) * 256 + lane * 8);
        float4 ha = hp[0], hb = hp[1];
        float hv[8] = {ha.x, ha.y, ha.z, ha.w, hb.x, hb.y, hb.z, hb.w};
        float accv[8];
#pragma unroll
        for (int tt = 0; tt < 8; tt++) {
            const float4* pq = (const float4*)&pp[tt][lane * 8];
            float4 pa = pq[0], pb = pq[1];
            float pv[8] = {pa.x, pa.y, pa.z, pa.w, pb.x, pb.y, pb.z, pb.w};
            float s = 0.f;
#pragma unroll
            for (int u = 0; u < 8; u++)
                s = fmaf(tanh_fast(hv[u] + pv[u]), wsr[u], s);
            accv[tt] = s;
        }
#pragma unroll
        for (int off = 16; off; off >>= 1)
#pragma unroll
            for (int tt = 0; tt < 8; tt++)
                accv[tt] += __shfl_xor_sync(0xffffffffu, accv[tt], off);
        if (lane < 8)
            scores[((long)(b * 512 + t0 + lane)) * 512 + l] = accv[lane] + wsb;
    }
}

// ---------------- softmax (rows of 512, in place) ----------------
__global__ void __launch_bounds__(256) softmax_kernel(float* __restrict__ s) {
    int row = blockIdx.x * 8 + (threadIdx.x >> 5);
    int lane = threadIdx.x & 31;
    float* p = s + (long)row * 512;
    float v[16];
    float m = -1e30f;
#pragma unroll
    for (int u = 0; u < 16; u++) { v[u] = p[u * 32 + lane]; m = fmaxf(m, v[u]); }
#pragma unroll
    for (int off = 16; off; off >>= 1) m = fmaxf(m, __shfl_xor_sync(0xffffffffu, m, off));
    float sum = 0.f;
#pragma unroll
    for (int u = 0; u < 16; u++) { v[u] = __expf(v[u] - m); sum += v[u]; }
#pragma unroll
    for (int off = 16; off; off >>= 1) sum += __shfl_xor_sync(0xffffffffu, sum, off);
    float inv = 1.0f / sum;
#pragma unroll
    for (int u = 0; u < 16; u++) p[u * 32 + lane] = v[u] * inv;
}

// ---------------- init recurrence state ----------------
__global__ void init_kernel() {
    int i = blockIdx.x * blockDim.x + threadIdx.x;
    if (i < 2 * 2 * Bz * Hz) ((float*)g_hstate)[i] = 0.f;
    if (i < 2) g_bar[i] = 0u;
}

// ---------------- recurrence: 64 persistent blocks (2 dirs x 32 slices) ----------------
__global__ void __launch_bounds__(256) recur_kernel(
    const float* __restrict__ gil, const float* __restrict__ gir,
    const float* __restrict__ Whh_l, const float* __restrict__ bhh_l,
    const float* __restrict__ Whh_r, const float* __restrict__ bhh_r,
    float* __restrict__ out)
{
    int dir = blockIdx.x >> 5;
    int slice = blockIdx.x & 31;
    int warp = threadIdx.x >> 5, lane = threadIdx.x & 31;
    int j = slice * 8 + warp;

    const float* Whh = dir ? Whh_r : Whh_l;
    const float* bhh = dir ? bhh_r : bhh_l;
    const float* gi  = dir ? gir : gil;

    float wr[8], wz[8], wn[8];
#pragma unroll
    for (int u = 0; u < 8; u += 4) {
        *(float4*)&wr[u] = *(const float4*)&Whh[(long)(j      ) * 256 + lane * 8 + u];
        *(float4*)&wz[u] = *(const float4*)&Whh[(long)(j + 256) * 256 + lane * 8 + u];
        *(float4*)&wn[u] = *(const float4*)&Whh[(long)(j + 512) * 256 + lane * 8 + u];
    }
    float br = bhh[j], bz = bhh[j + 256], bn = bhh[j + 512];

    float* hbuf = &g_hstate[dir][0][0];
    unsigned* bar = &g_bar[dir];

    for (int s = 0; s < 512; s++) {
        int t = dir ? (511 - s) : s;
        const float* hc = hbuf + (s & 1) * (Bz * Hz);
        float* hnb      = hbuf + ((s + 1) & 1) * (Bz * Hz);

        float my_sr = 0.f, my_sz = 0.f, my_sn = 0.f;
#pragma unroll 4
        for (int b = 0; b < 32; b++) {
            float4 h0 = __ldcg((const float4*)(hc + b * 256 + lane * 8));
            float4 h1 = __ldcg((const float4*)(hc + b * 256 + lane * 8 + 4));
            float hv[8] = {h0.x, h0.y, h0.z, h0.w, h1.x, h1.y, h1.z, h1.w};
            float sr = 0.f, sz = 0.f, sn = 0.f;
#pragma unroll
            for (int u = 0; u < 8; u++) {
                sr = fmaf(wr[u], hv[u], sr);
                sz = fmaf(wz[u], hv[u], sz);
                sn = fmaf(wn[u], hv[u], sn);
            }
#pragma unroll
            for (int off = 16; off; off >>= 1) {
                sr += __shfl_xor_sync(0xffffffffu, sr, off);
                sz += __shfl_xor_sync(0xffffffffu, sz, off);
                sn += __shfl_xor_sync(0xffffffffu, sn, off);
            }
            if (lane == b) { my_sr = sr; my_sz = sz; my_sn = sn; }
        }
        // epilogue: this lane handles batch b = lane
        {
            long gbase = ((long)(lane * 512 + t)) * 768 + j;
            float gr_ = __ldg(gi + gbase);
            float gz_ = __ldg(gi + gbase + 256);
            float gn_ = __ldg(gi + gbase + 512);
            float hprev = __ldcg(hc + lane * 256 + j);
            float r = sigmoidf_(gr_ + br + my_sr);
            float z = sigmoidf_(gz_ + bz + my_sz);
            float n = tanhf(gn_ + r * (bn + my_sn));
            float hnew = (1.0f - z) * n + z * hprev;
            __stcg(hnb + lane * 256 + j, hnew);
            out[((long)(lane * 512 + t)) * 512 + dir * 256 + j] = hnew;
        }
        // inter-block barrier (per direction): syncthreads gives hb-ordering of
        // all block writes before thread0's gpu-scope release arrival.
        __syncthreads();
        if (threadIdx.x == 0) {
            red_release_add(bar, 1u);
            unsigned target = 32u * (unsigned)(s + 1);
            while (ld_acq(bar) < target) { }   // tight L2 spin, no nanosleep
        }
        __syncthreads();
    }
}

// ---------------- host launcher ----------------
extern "C" void kernel_launch(void* const* d_in, const int* in_sizes, int n_in,
                              void* d_out, int out_size) {
    const float* P     = (const float*)d_in[0];
    const float* wq_w  = (const float*)d_in[1];
    const float* wq_b  = (const float*)d_in[2];
    const float* wp_w  = (const float*)d_in[3];
    const float* wp_b  = (const float*)d_in[4];
    const float* ws_w  = (const float*)d_in[5];
    const float* ws_b  = (const float*)d_in[6];
    const float* wg_w  = (const float*)d_in[7];
    const float* wg_b  = (const float*)d_in[8];
    const float* Wih_l = (const float*)d_in[9];
    const float* Whh_l = (const float*)d_in[10];
    const float* bih_l = (const float*)d_in[11];
    const float* bhh_l = (const float*)d_in[12];
    const float* Wih_r = (const float*)d_in[13];
    const float* Whh_r = (const float*)d_in[14];
    const float* bih_r = (const float*)d_in[15];
    const float* bhh_r = (const float*)d_in[16];
    float* out = (float*)d_out;

    float *pHq, *pPp, *pScores, *pPC, *pCg, *pGil, *pGir;
    cudaGetSymbolAddress((void**)&pHq, g_Hq);
    cudaGetSymbolAddress((void**)&pPp, g_Pp);
    cudaGetSymbolAddress((void**)&pScores, g_scores);
    cudaGetSymbolAddress((void**)&pPC, g_PC);
    cudaGetSymbolAddress((void**)&pCg, g_Cg);
    cudaGetSymbolAddress((void**)&pGil, g_gil);
    cudaGetSymbolAddress((void**)&pGir, g_gir);

    // Phase A
    sgemm_kernel<1,0><<<dim3(2,128,1), 256>>>(P, wq_w, wq_b, nullptr, pHq,
        ML, 256, 256, 0, 0, 0, 256, 0);
    sgemm_kernel<1,0><<<dim3(2,128,1), 256>>>(P, wp_w, wp_b, nullptr, pPp,
        ML, 256, 256, 0, 0, 0, 256, 0);
    copyP_kernel<<<ML*256/4/256, 256>>>(P, pPC);
    scores_kernel<<<dim3(64,32), 256>>>(pHq, pPp, ws_w, ws_b, pScores);
    softmax_kernel<<<ML/8, 256>>>(pScores);
    // context per-b: C = attn @ P  -> PC[:, 256:512]
    sgemm_kernel<0,2><<<dim3(2,4,32), 256>>>(pScores, P, nullptr, nullptr, pPC,
        512, 256, 512, (long)512*512, (long)512*256, (long)512*512, 512, 256);
    // gate: Cg = sigmoid(PC @ wg^T + b) * C
    sgemm_kernel<1,1><<<dim3(2,128,1), 256>>>(pPC, wg_w, wg_b, pPC, pCg,
        ML, 256, 512, 0, 0, 0, 256, 0);
    // GRU input projections
    sgemm_kernel<1,0><<<dim3(6,128,1), 256>>>(pCg, Wih_l, bih_l, nullptr, pGil,
        ML, 768, 256, 0, 0, 0, 768, 0);
    sgemm_kernel<1,0><<<dim3(6,128,1), 256>>>(pCg, Wih_r, bih_r, nullptr, pGir,
        ML, 768, 256, 0, 0, 0, 768, 0);

    // Phase B
    init_kernel<<<128, 256>>>();
    recur_kernel<<<64, 256>>>(pGil, pGir, Whh_l, bhh_l, Whh_r, bhh_r, out);
}

// round 8
// speedup vs baseline: 1.8594x; 1.8594x over previous
#include <cuda_runtime.h>
#include <cuda_bf16.h>
#include <cstdint>

// Problem constants
#define Bz 32
#define Lz 512
#define Hz 256
#define ML (Bz*Lz)          // 16384 rows

// ---------------- device scratch ----------------
__device__ float g_Hq[ML*Hz];
__device__ float g_Pp[ML*Hz];
__device__ float g_scores[Bz*Lz*Lz];     // reused in-place as attn
__device__ float g_PC[ML*2*Hz];          // [P | C] concat
__device__ float g_Cg[ML*Hz];            // gated context
__device__ float g_gilT[Lz*3*Hz*Bz];     // [t][g*256+j][b]
__device__ float g_girT[Lz*3*Hz*Bz];
__device__ float g_ht[2][2][Hz*Bz];      // [dir][buf][j*32+b]  (transposed h)
__device__ unsigned g_bar[2];

// ---------------- helpers ----------------
__device__ __forceinline__ float tanh_fast(float x) {
    float y; asm("tanh.approx.f32 %0, %1;" : "=f"(y) : "f"(x)); return y;
}
__device__ __forceinline__ float sigmoidf_(float x) {
    return 1.0f / (1.0f + __expf(-x));
}
__device__ __forceinline__ unsigned ld_acq(const unsigned* p) {
    unsigned v; asm volatile("ld.acquire.gpu.global.u32 %0, [%1];" : "=r"(v) : "l"(p)); return v;
}
__device__ __forceinline__ void red_release_add(unsigned* p, unsigned v) {
    asm volatile("red.release.gpu.global.add.u32 [%0], %1;" :: "l"(p), "r"(v) : "memory");
}

// ---------------- generic SGEMM ----------------
// TRANSB=1: B is N x K (row-major), compute A@B^T.  TRANSB=0: B is K x N.
// EPI 0: +bias  ; EPI 1: sigmoid(acc+bias)*aux[row*512+256+col] ; EPI 2: plain
// EPI 3: +bias, scatter to giT layout: [(t*768+col)*32 + b], row = b*512+t
#define BMt 128
#define BNt 128
#define BKt 16
template<int TRANSB, int EPI>
__global__ void __launch_bounds__(256, 2) sgemm_kernel(
    const float* __restrict__ A, const float* __restrict__ Bm,
    const float* __restrict__ bias, const float* __restrict__ aux,
    float* __restrict__ Cc,
    int M, int N, int K,
    long sA, long sB, long sC, int ldc, int coff)
{
    __shared__ float As[BKt][BMt];
    __shared__ float Bs[BKt][BNt];
    int z = blockIdx.z;
    A  += z * sA;
    Bm += z * sB;
    long cbase = (long)z * sC;
    int m0 = blockIdx.y * BMt, n0 = blockIdx.x * BNt;
    int tid = threadIdx.x;

    int arow = tid >> 2;          // 0..63
    int akk  = (tid & 3) * 4;     // 0,4,8,12
    int bkk  = tid >> 5;          // 0..7
    int bcol = (tid & 31) * 4;    // 0..124

    float acc[8][8];
#pragma unroll
    for (int i = 0; i < 8; i++)
#pragma unroll
        for (int j = 0; j < 8; j++) acc[i][j] = 0.f;

    int tr = tid >> 4, tc = tid & 15;

    for (int k0 = 0; k0 < K; k0 += BKt) {
        float4 a0 = *(const float4*)&A[(long)(m0 + arow) * K + k0 + akk];
        float4 a1 = *(const float4*)&A[(long)(m0 + arow + 64) * K + k0 + akk];
        As[akk+0][arow] = a0.x; As[akk+1][arow] = a0.y; As[akk+2][arow] = a0.z; As[akk+3][arow] = a0.w;
        As[akk+0][arow+64] = a1.x; As[akk+1][arow+64] = a1.y; As[akk+2][arow+64] = a1.z; As[akk+3][arow+64] = a1.w;
        if (TRANSB) {
            float4 b0 = *(const float4*)&Bm[(long)(n0 + arow) * K + k0 + akk];
            float4 b1 = *(const float4*)&Bm[(long)(n0 + arow + 64) * K + k0 + akk];
            Bs[akk+0][arow] = b0.x; Bs[akk+1][arow] = b0.y; Bs[akk+2][arow] = b0.z; Bs[akk+3][arow] = b0.w;
            Bs[akk+0][arow+64] = b1.x; Bs[akk+1][arow+64] = b1.y; Bs[akk+2][arow+64] = b1.z; Bs[akk+3][arow+64] = b1.w;
        } else {
            float4 b0 = *(const float4*)&Bm[(long)(k0 + bkk) * N + n0 + bcol];
            float4 b1 = *(const float4*)&Bm[(long)(k0 + bkk + 8) * N + n0 + bcol];
            *(float4*)&Bs[bkk][bcol]     = b0;
            *(float4*)&Bs[bkk+8][bcol]   = b1;
        }
        __syncthreads();
#pragma unroll
        for (int kk = 0; kk < BKt; kk++) {
            float a[8], b[8];
            *(float4*)&a[0] = *(float4*)&As[kk][tr*8];
            *(float4*)&a[4] = *(float4*)&As[kk][tr*8+4];
            *(float4*)&b[0] = *(float4*)&Bs[kk][tc*8];
            *(float4*)&b[4] = *(float4*)&Bs[kk][tc*8+4];
#pragma unroll
            for (int i = 0; i < 8; i++)
#pragma unroll
                for (int j = 0; j < 8; j++) acc[i][j] = fmaf(a[i], b[j], acc[i][j]);
        }
        __syncthreads();
    }
#pragma unroll
    for (int i = 0; i < 8; i++) {
        int row = m0 + tr*8 + i;
#pragma unroll
        for (int j = 0; j < 8; j++) {
            int col = n0 + tc*8 + j;
            float v = acc[i][j];
            if (EPI == 0) {
                v += bias[col];
                Cc[cbase + (long)row * ldc + coff + col] = v;
            } else if (EPI == 1) {
                float g = sigmoidf_(v + bias[col]);
                Cc[cbase + (long)row * ldc + coff + col] = g * aux[(long)row * 512 + 256 + col];
            } else if (EPI == 2) {
                Cc[cbase + (long)row * ldc + coff + col] = v;
            } else { // EPI == 3 : giT scatter
                v += bias[col];
                int b = row >> 9, t = row & 511;
                Cc[((long)t * 768 + col) * 32 + b] = v;
            }
        }
    }
}

// ---------------- copy P into PC[:, :256] ----------------
__global__ void copyP_kernel(const float* __restrict__ P, float* __restrict__ PC) {
    int i = blockIdx.x * blockDim.x + threadIdx.x;
    int r = i >> 6;
    int c4 = i & 63;
    ((float4*)PC)[(long)r * 128 + c4] = ((const float4*)P)[i];
}

// ---------------- scores ----------------
__global__ void __launch_bounds__(256) scores_kernel(
    const float* __restrict__ Hq, const float* __restrict__ Pp,
    const float* __restrict__ ws_w, const float* __restrict__ ws_b,
    float* __restrict__ scores)
{
    __shared__ float pp[8][256];
    __shared__ float wss[256];
    int b = blockIdx.y;
    int t0 = blockIdx.x * 8;
    int tid = threadIdx.x;
    for (int idx = tid; idx < 8 * 256; idx += 256) {
        int tt = idx >> 8, h = idx & 255;
        pp[tt][h] = Pp[((long)(b * 512 + t0 + tt)) * 256 + h];
    }
    if (tid < 256) wss[tid] = ws_w[tid];
    __syncthreads();
    float wsb = __ldg(ws_b);
    int warp = tid >> 5, lane = tid & 31;
    float wsr[8];
#pragma unroll
    for (int u = 0; u < 8; u++) wsr[u] = wss[lane * 8 + u];

    for (int l = warp; l < 512; l += 8) {
        const float4* hp = (const float4*)(Hq + ((long)(b * 512 + l)) * 256 + lane * 8);
        float4 ha = hp[0], hb = hp[1];
        float hv[8] = {ha.x, ha.y, ha.z, ha.w, hb.x, hb.y, hb.z, hb.w};
        float accv[8];
#pragma unroll
        for (int tt = 0; tt < 8; tt++) {
            const float4* pq = (const float4*)&pp[tt][lane * 8];
            float4 pa = pq[0], pb = pq[1];
            float pv[8] = {pa.x, pa.y, pa.z, pa.w, pb.x, pb.y, pb.z, pb.w};
            float s = 0.f;
#pragma unroll
            for (int u = 0; u < 8; u++)
                s = fmaf(tanh_fast(hv[u] + pv[u]), wsr[u], s);
            accv[tt] = s;
        }
#pragma unroll
        for (int off = 16; off; off >>= 1)
#pragma unroll
            for (int tt = 0; tt < 8; tt++)
                accv[tt] += __shfl_xor_sync(0xffffffffu, accv[tt], off);
        if (lane < 8)
            scores[((long)(b * 512 + t0 + lane)) * 512 + l] = accv[lane] + wsb;
    }
}

// ---------------- softmax ----------------
__global__ void __launch_bounds__(256) softmax_kernel(float* __restrict__ s) {
    int row = blockIdx.x * 8 + (threadIdx.x >> 5);
    int lane = threadIdx.x & 31;
    float* p = s + (long)row * 512;
    float v[16];
    float m = -1e30f;
#pragma unroll
    for (int u = 0; u < 16; u++) { v[u] = p[u * 32 + lane]; m = fmaxf(m, v[u]); }
#pragma unroll
    for (int off = 16; off; off >>= 1) m = fmaxf(m, __shfl_xor_sync(0xffffffffu, m, off));
    float sum = 0.f;
#pragma unroll
    for (int u = 0; u < 16; u++) { v[u] = __expf(v[u] - m); sum += v[u]; }
#pragma unroll
    for (int off = 16; off; off >>= 1) sum += __shfl_xor_sync(0xffffffffu, sum, off);
    float inv = 1.0f / sum;
#pragma unroll
    for (int u = 0; u < 16; u++) p[u * 32 + lane] = v[u] * inv;
}

// ---------------- init recurrence state ----------------
__global__ void init_kernel() {
    int i = blockIdx.x * blockDim.x + threadIdx.x;
    if (i < 2 * 2 * Hz * Bz) ((float*)g_ht)[i] = 0.f;
    if (i < 2) g_bar[i] = 0u;
}

// ---------------- recurrence v2: 128 blocks (2 dirs x 64), 128 thr, warp=j lane=b ----
__global__ void __launch_bounds__(128, 1) recur_kernel(
    const float* __restrict__ Whh_l, const float* __restrict__ bhh_l,
    const float* __restrict__ Whh_r, const float* __restrict__ bhh_r,
    float* __restrict__ out)
{
    __shared__ float ht[Hz * Bz];          // [k][b], 32KB
    __shared__ float wsm[4 * 3 * 256];     // [jl][g][k], 12KB

    int dir   = blockIdx.x >> 6;
    int slice = blockIdx.x & 63;
    int tid   = threadIdx.x;
    int warp  = tid >> 5, lane = tid & 31;
    int j = slice * 4 + warp;

    const float* Whh = dir ? Whh_r : Whh_l;
    const float* bhh = dir ? bhh_r : bhh_l;
    const float* giT = dir ? g_girT : g_gilT;

    // preload weights (step-invariant) into smem
    for (int idx = tid; idx < 3072; idx += 128) {
        int jl  = idx / 768;
        int rem = idx - jl * 768;
        int g   = rem >> 8;
        int k   = rem & 255;
        wsm[idx] = Whh[((g << 8) + slice * 4 + jl) * 256 + k];
    }
    float br = bhh[j], bz = bhh[j + 256], bn = bhh[j + 512];
    const float* wp = &wsm[warp * 768];

    unsigned* bar = &g_bar[dir];

    for (int s = 0; s < 512; s++) {
        int t = dir ? (511 - s) : s;
        const float4* hsrc = (const float4*)(&g_ht[dir][s & 1][0]);
        // stage h (transposed [k][b]) into smem, L1-bypassed
#pragma unroll
        for (int i = 0; i < 16; i++)
            ((float4*)ht)[tid + i * 128] = __ldcg(&hsrc[tid + i * 128]);
        __syncthreads();

        float sr0 = 0.f, sz0 = 0.f, sn0 = 0.f;
        float sr1 = 0.f, sz1 = 0.f, sn1 = 0.f;
#pragma unroll 8
        for (int k = 0; k < 256; k += 4) {
            float h0 = ht[(k + 0) * 32 + lane];
            float h1 = ht[(k + 1) * 32 + lane];
            float h2 = ht[(k + 2) * 32 + lane];
            float h3 = ht[(k + 3) * 32 + lane];
            float4 wr = *(const float4*)&wp[k];
            float4 wz = *(const float4*)&wp[256 + k];
            float4 wn = *(const float4*)&wp[512 + k];
            sr0 = fmaf(wr.x, h0, sr0); sr1 = fmaf(wr.y, h1, sr1);
            sr0 = fmaf(wr.z, h2, sr0); sr1 = fmaf(wr.w, h3, sr1);
            sz0 = fmaf(wz.x, h0, sz0); sz1 = fmaf(wz.y, h1, sz1);
            sz0 = fmaf(wz.z, h2, sz0); sz1 = fmaf(wz.w, h3, sz1);
            sn0 = fmaf(wn.x, h0, sn0); sn1 = fmaf(wn.y, h1, sn1);
            sn0 = fmaf(wn.z, h2, sn0); sn1 = fmaf(wn.w, h3, sn1);
        }
        float sr = sr0 + sr1, sz = sz0 + sz1, sn = sn0 + sn1;

        // epilogue: lane = batch b
        long gbase = ((long)t * 768 + j) * 32 + lane;
        float gr_ = __ldg(giT + gbase);
        float gz_ = __ldg(giT + gbase + 256 * 32);
        float gn_ = __ldg(giT + gbase + 512 * 32);
        float hprev = ht[j * 32 + lane];
        float r = sigmoidf_(gr_ + br + sr);
        float z = sigmoidf_(gz_ + bz + sz);
        float n = tanh_fast(gn_ + r * (bn + sn));
        float hnew = (1.0f - z) * n + z * hprev;
        __stcg(&g_ht[dir][(s + 1) & 1][j * 32 + lane], hnew);
        out[((long)(lane * 512 + t)) * 512 + dir * 256 + j] = hnew;

        // inter-block barrier (per direction)
        __syncthreads();
        if (tid == 0) {
            red_release_add(bar, 1u);
            unsigned target = 64u * (unsigned)(s + 1);
            while (ld_acq(bar) < target) { }
        }
        __syncthreads();
    }
}

// ---------------- host launcher ----------------
extern "C" void kernel_launch(void* const* d_in, const int* in_sizes, int n_in,
                              void* d_out, int out_size) {
    const float* P     = (const float*)d_in[0];
    const float* wq_w  = (const float*)d_in[1];
    const float* wq_b  = (const float*)d_in[2];
    const float* wp_w  = (const float*)d_in[3];
    const float* wp_b  = (const float*)d_in[4];
    const float* ws_w  = (const float*)d_in[5];
    const float* ws_b  = (const float*)d_in[6];
    const float* wg_w  = (const float*)d_in[7];
    const float* wg_b  = (const float*)d_in[8];
    const float* Wih_l = (const float*)d_in[9];
    const float* Whh_l = (const float*)d_in[10];
    const float* bih_l = (const float*)d_in[11];
    const float* bhh_l = (const float*)d_in[12];
    const float* Wih_r = (const float*)d_in[13];
    const float* Whh_r = (const float*)d_in[14];
    const float* bih_r = (const float*)d_in[15];
    const float* bhh_r = (const float*)d_in[16];
    float* out = (float*)d_out;

    float *pHq, *pPp, *pScores, *pPC, *pCg, *pGilT, *pGirT;
    cudaGetSymbolAddress((void**)&pHq, g_Hq);
    cudaGetSymbolAddress((void**)&pPp, g_Pp);
    cudaGetSymbolAddress((void**)&pScores, g_scores);
    cudaGetSymbolAddress((void**)&pPC, g_PC);
    cudaGetSymbolAddress((void**)&pCg, g_Cg);
    cudaGetSymbolAddress((void**)&pGilT, g_gilT);
    cudaGetSymbolAddress((void**)&pGirT, g_girT);

    // Phase A
    sgemm_kernel<1,0><<<dim3(2,128,1), 256>>>(P, wq_w, wq_b, nullptr, pHq,
        ML, 256, 256, 0, 0, 0, 256, 0);
    sgemm_kernel<1,0><<<dim3(2,128,1), 256>>>(P, wp_w, wp_b, nullptr, pPp,
        ML, 256, 256, 0, 0, 0, 256, 0);
    copyP_kernel<<<ML*256/4/256, 256>>>(P, pPC);
    scores_kernel<<<dim3(64,32), 256>>>(pHq, pPp, ws_w, ws_b, pScores);
    softmax_kernel<<<ML/8, 256>>>(pScores);
    // context per-b: C = attn @ P  -> PC[:, 256:512]
    sgemm_kernel<0,2><<<dim3(2,4,32), 256>>>(pScores, P, nullptr, nullptr, pPC,
        512, 256, 512, (long)512*512, (long)512*256, (long)512*512, 512, 256);
    // gate: Cg = sigmoid(PC @ wg^T + b) * C
    sgemm_kernel<1,1><<<dim3(2,128,1), 256>>>(pPC, wg_w, wg_b, pPC, pCg,
        ML, 256, 512, 0, 0, 0, 256, 0);
    // GRU input projections -> transposed giT layout
    sgemm_kernel<1,3><<<dim3(6,128,1), 256>>>(pCg, Wih_l, bih_l, nullptr, pGilT,
        ML, 768, 256, 0, 0, 0, 0, 0);
    sgemm_kernel<1,3><<<dim3(6,128,1), 256>>>(pCg, Wih_r, bih_r, nullptr, pGirT,
        ML, 768, 256, 0, 0, 0, 0, 0);

    // Phase B
    init_kernel<<<128, 256>>>();
    recur_kernel<<<128, 128>>>(Whh_l, bhh_l, Whh_r, bhh_r, out);
}